// round 7
// baseline (speedup 1.0000x reference)
#include <cuda_runtime.h>

// ---------------------------------------------------------------------------
// out[i, j] = f(j-1) - f(j),  f(j) = relu(1 - relu(x_full[j+1] - x_i) /
//                                         (x_full[j+1] - x_full[j] + 1e-9))
// sentinels f(-1)=1, f(n_full-1)=0.  The formula is EXACTLY 0 outside a
// <=8-column window around x's interval, so:
//   pass 1: zero the whole 8-row stripe branch-free (pure STG.128 stream,
//           16B-aligned since 8*n_full*4 % 16 == 0)
//   pass 2: patch the <=3 window chunks per row; each chunk is patched by
//           the SAME lane (t & 31) that zeroed it, so same-thread store
//           ordering guarantees the final value wins. No syncs needed.
// ---------------------------------------------------------------------------

#define ROWS_PER_WARP 8

__device__ __forceinline__ float evalf_s(const float* __restrict__ sxf,
                                         int j, int n_full, float x) {
    if (j < 0) return 1.0f;
    if (j >= n_full - 1) return 0.0f;
    float xa = sxf[j];
    float xb = sxf[j + 1];
    float t  = fmaxf(0.f, xb - x);
    return fmaxf(0.f, 1.0f - t / (xb - xa + 1e-9f));
}

__device__ __forceinline__ float value_s(const float* __restrict__ sxf,
                                         int c, int n_full, float x) {
    return evalf_s(sxf, c - 1, n_full, x) - evalf_s(sxf, c, n_full, x);
}

__global__ void fused_kernel(const float* __restrict__ x_eval,
                             const float* __restrict__ x_full,
                             float* __restrict__ out,
                             int n_points, int n_full) {
    extern __shared__ float sxf[];                 // n_full floats
    for (int m = threadIdx.x; m < n_full; m += blockDim.x)
        sxf[m] = x_full[m];
    __syncthreads();

    int gwarp = (blockIdx.x * blockDim.x + threadIdx.x) >> 5;
    int lane  = threadIdx.x & 31;

    int r0 = gwarp * ROWS_PER_WARP;                // first row of stripe
    if (r0 >= n_points) return;
    int nrows = n_points - r0;
    if (nrows > ROWS_PER_WARP) nrows = ROWS_PER_WARP;

    // ---- per-lane search: lane i finds interval for row r0+i -------------
    int wlo = 1, whi = 0;                          // empty range default
    if (lane < nrows) {
        float x = __ldg(x_eval + r0 + lane);
        int lo = 0, hi = n_full;
        while (lo < hi) {
            int mid = (lo + hi) >> 1;
            if (sxf[mid] <= x) lo = mid + 1;
            else hi = mid;
        }
        int k = lo - 1;
        k = (k < 0) ? 0 : k;
        if (k > n_full - 2) k = n_full - 2;
        int j0 = (k - 2 < 0) ? 0 : (k - 2);
        int j1 = (k + 5 > n_full - 1) ? (n_full - 1) : (k + 5);
        // window chunk range in stripe-flat float4 coords
        wlo = (lane * n_full + j0) >> 2;
        whi = (lane * n_full + j1) >> 2;
    }

    // ---- pass 1: branch-free zero stream over the stripe -----------------
    long long sbase = (long long)r0 * n_full;      // stripe base (floats)
    int n_flat = nrows * n_full;
    int n4     = n_flat >> 2;                      // 16B-aligned chunk count
    int tail   = n_flat & 3;                       // only on partial stripes
    float4* o4 = reinterpret_cast<float4*>(out + sbase);

    const float4 z = make_float4(0.f, 0.f, 0.f, 0.f);
    #pragma unroll 4
    for (int t = lane; t < n4; t += 32)
        __stcs(o4 + t, z);

    if (lane < tail) {                             // tail: exact formula
        int p = n4 * 4 + lane;
        int rr = p / n_full, cc = p - rr * n_full;
        out[sbase + p] = value_s(sxf, cc, n_full, __ldg(x_eval + r0 + rr));
    }

    // ---- pass 2: patch window chunks (same lane as zero pass) ------------
    #pragma unroll
    for (int i = 0; i < ROWS_PER_WARP; ++i) {
        if (i >= nrows) break;
        int wl = __shfl_sync(0xffffffffu, wlo, i);
        int wh = __shfl_sync(0xffffffffu, whi, i);
        for (int wc = wl; wc <= wh; ++wc) {
            if ((wc & 31) == lane && wc < n4) {
                int p = wc << 2;                   // stripe-flat float index
                float4 v;
                #pragma unroll
                for (int e = 0; e < 4; ++e) {
                    int pe = p + e;
                    int rr = pe / n_full;          // true row of element
                    int cc = pe - rr * n_full;
                    float xe = __ldg(x_eval + r0 + rr);
                    ((float*)&v)[e] = value_s(sxf, cc, n_full, xe);
                }
                __stcs(o4 + wc, v);                // overwrites its own zero
            }
        }
    }
}

extern "C" void kernel_launch(void* const* d_in, const int* in_sizes, int n_in,
                              void* d_out, int out_size) {
    const float* x_eval = (const float*)d_in[0];  // (n_points, 1) float32
    const float* x_full = (const float*)d_in[1];  // (n_full,)    float32 sorted
    float* out = (float*)d_out;                   // (n_points, n_full) float32

    int n_points = in_sizes[0];
    int n_full   = in_sizes[1];

    int threads = 256;                             // 8 warps/block
    int rows_per_block = (threads / 32) * ROWS_PER_WARP;   // 64
    int blocks = (n_points + rows_per_block - 1) / rows_per_block;
    size_t smem = (size_t)n_full * sizeof(float);

    fused_kernel<<<blocks, threads, smem>>>(x_eval, x_full, out,
                                            n_points, n_full);
}

// round 8
// speedup vs baseline: 1.3418x; 1.3418x over previous
#include <cuda_runtime.h>

// ---------------------------------------------------------------------------
// out[i, j] = f(j-1) - f(j),  f(j) = relu(1 - relu(x_full[j+1] - x_i) /
//                                         (x_full[j+1] - x_full[j] + 1e-9))
// sentinels f(-1)=1, f(n_full-1)=0.  Nonzeros confined to j in [k-2, k+5]
// where k = interval(x_i).  Fused single kernel, ONE float4 chunk per thread
// (the empirically fastest store-stream shape):
//   fast path: x outside [x_full[cc-6], x_full[cc+7]]  ->  STG.128 zero
//   slow path (~1.5%): evaluate the exact formula for the 4 columns directly
//     (no search needed anywhere).
// ---------------------------------------------------------------------------

__device__ __forceinline__ float evalf_g(const float* __restrict__ xf,
                                         int j, int n_full, float x) {
    if (j < 0) return 1.0f;
    if (j >= n_full - 1) return 0.0f;
    float xa = __ldg(xf + j);
    float xb = __ldg(xf + j + 1);
    float t  = fmaxf(0.f, xb - x);
    return fmaxf(0.f, 1.0f - t / (xb - xa + 1e-9f));
}

__device__ __forceinline__ float value_g(const float* __restrict__ xf,
                                         int c, int n_full, float x) {
    return evalf_g(xf, c - 1, n_full, x) - evalf_g(xf, c, n_full, x);
}

__global__ void fused_kernel(const float* __restrict__ x_eval,
                             const float* __restrict__ x_full,
                             float* __restrict__ out,
                             int n_points, int n_full,
                             int n4, int tail,
                             unsigned magic, int mshift) {
    int t = blockIdx.x * blockDim.x + threadIdx.x;
    if (t >= n4) {
        // one thread handles the scalar tail (total % 4), exact formula
        if (t == n4 && tail) {
            for (int e = 0; e < tail; ++e) {
                int p  = n4 * 4 + e;
                int rr = (int)(__umulhi((unsigned)p, magic) >> mshift);
                int cc = p - rr * n_full;
                if (cc >= n_full) { cc -= n_full; ++rr; }
                out[p] = value_g(x_full, cc, n_full, __ldg(x_eval + rr));
            }
        }
        return;
    }

    int p  = t << 2;                               // first flat element
    int rr = (int)(__umulhi((unsigned)p, magic) >> mshift);
    int cc = p - rr * n_full;
    if (cc >= n_full) { cc -= n_full; ++rr; }      // magic-div fixup (<=1)

    float x = __ldg(x_eval + rr);                  // broadcast within warp

    // conservative window test (margins cover the [k-2,k+5] window + eps)
    int ilo = cc - 6;  if (ilo < 0) ilo = 0;
    int ihi = cc + 7;  if (ihi > n_full - 1) ihi = n_full - 1;
    float xlo = __ldg(x_full + ilo);
    float xhi = __ldg(x_full + ihi);

    // edge chunks (clamped bounds can't certify zero) always take slow path
    bool edge = (cc < 12) | (cc > n_full - 13);
    bool slow = edge | ((x >= xlo) & (x <= xhi));

    float4 v = make_float4(0.f, 0.f, 0.f, 0.f);
    if (slow) {                                    // ~1.5% of threads
        // chunk may straddle a row boundary: recompute (rr, cc) per element
        #pragma unroll
        for (int e = 0; e < 4; ++e) {
            int pe = p + e;
            int re = rr, ce = cc + e;
            if (ce >= n_full) { ce -= n_full; ++re; }
            float xe = (re == rr) ? x : __ldg(x_eval + re);
            ((float*)&v)[e] = value_g(x_full, ce, n_full, xe);
        }
    }
    __stcs(reinterpret_cast<float4*>(out) + t, v);
}

extern "C" void kernel_launch(void* const* d_in, const int* in_sizes, int n_in,
                              void* d_out, int out_size) {
    const float* x_eval = (const float*)d_in[0];  // (n_points, 1) float32
    const float* x_full = (const float*)d_in[1];  // (n_full,)    float32 sorted
    float* out = (float*)d_out;                   // (n_points, n_full) float32

    int n_points = in_sizes[0];
    int n_full   = in_sizes[1];
    (void)n_points;

    int total = out_size;
    int n4    = total >> 2;
    int tail  = total & 3;

    // floor magic for division by n_full: q = umulhi(p, M) >> s, then one
    // fixup.  s chosen so M < 2^32;  p < 2^31.
    int s = 0;
    while ((1ull << (32 + s)) / (unsigned)n_full < (1ull << 31)) ++s;
    unsigned magic = (unsigned)((1ull << (32 + s)) / (unsigned)n_full);

    int threads = 256;
    int blocks  = (n4 + 1 + threads - 1) / threads;   // +1 for tail thread
    fused_kernel<<<blocks, threads>>>(x_eval, x_full, out,
                                      n_points, n_full, n4, tail,
                                      magic, s);
}

// round 9
// speedup vs baseline: 2.0210x; 1.5062x over previous
#include <cuda_runtime.h>

// ---------------------------------------------------------------------------
// out[i, j] = f(j-1) - f(j),  f(j) = relu(1 - relu(x_full[j+1] - x_i) /
//                                         (x_full[j+1] - x_full[j] + 1e-9))
// sentinels f(-1)=1, f(n_full-1)=0.  Nonzeros only in j in [k-2, k+5],
// k = interval(x_i).  One warp per row:
//   - warp-parallel 32-ary search via ballot (3 rounds, 3 LDGs)
//   - branch-free STG.128 zero of the entire row (hot loop == zero kernel)
//   - same-lane patch of the <=3 window chunks (program-order overwrite)
// ---------------------------------------------------------------------------

__device__ __forceinline__ float evalf_g(const float* __restrict__ xf,
                                         int j, int n_full, float x) {
    if (j < 0) return 1.0f;
    if (j >= n_full - 1) return 0.0f;
    float xa = __ldg(xf + j);
    float xb = __ldg(xf + j + 1);
    float t  = fmaxf(0.f, xb - x);
    return fmaxf(0.f, 1.0f - t / (xb - xa + 1e-9f));
}

__device__ __forceinline__ float value_g(const float* __restrict__ xf,
                                         int c, int n_full, float x) {
    return evalf_g(xf, c - 1, n_full, x) - evalf_g(xf, c, n_full, x);
}

__global__ void __launch_bounds__(256)
fused_kernel(const float* __restrict__ x_eval,
             const float* __restrict__ x_full,
             float* __restrict__ out,
             int n_points, int n_full) {
    int gwarp = (blockIdx.x * blockDim.x + threadIdx.x) >> 5;
    int lane  = threadIdx.x & 31;
    if (gwarp >= n_points) return;             // warp-uniform exit

    float x = __ldg(x_eval + gwarp);           // broadcast

    // ---- 32-ary warp search: k0 = max{m : x_full[m] <= x}, else -1 -------
    const unsigned FULL = 0xffffffffu;
    int n  = n_full;
    int s1 = (n + 31) >> 5;                    // 65 @ n=2049
    int m1 = lane * s1;
    bool t1 = (m1 <= n - 1) && (__ldg(x_full + min(m1, n - 1)) <= x);
    unsigned b1 = __ballot_sync(FULL, t1);
    int k0;
    if (b1 == 0) {
        k0 = -1;
    } else {
        int A    = (31 - __clz(b1)) * s1;      // x_full[A] <= x
        int rem  = min(s1, n - A);             // range size incl A
        int s2   = (rem + 31) >> 5;            // <= 3
        bool t2  = (lane * s2 < rem) &&
                   (__ldg(x_full + min(A + lane * s2, n - 1)) <= x);
        unsigned b2 = __ballot_sync(FULL, t2); // lane0 always set
        int A2   = A + (31 - __clz(b2)) * s2;
        int rem2 = min(s2, rem - ((31 - __clz(b2)) * s2));
        bool t3  = (lane < rem2) &&
                   (__ldg(x_full + min(A2 + lane, n - 1)) <= x);
        unsigned b3 = __ballot_sync(FULL, t3); // lane0 always set
        k0 = A2 + (31 - __clz(b3));
    }
    int k = k0 < 0 ? 0 : k0;
    if (k > n - 2) k = n - 2;
    int j0 = (k - 2 < 0) ? 0 : (k - 2);
    int j1 = (k + 5 > n - 1) ? (n - 1) : (k + 5);

    // ---- row layout (rows are only 4B aligned: n_full odd) ---------------
    int base = gwarp * n;                      // < 2^31
    int head = (-base) & 3;                    // scalars to reach 16B align
    if (head > n) head = n;
    int n_rem = n - head;
    int n4c   = n_rem >> 2;
    int tailc = n_rem & 3;
    float4* o4 = reinterpret_cast<float4*>(out + base + head);

    if (lane < head)                           // head: exact formula
        out[base + lane] = value_g(x_full, lane, n, x);

    // ---- branch-free zero of the whole row (the hot loop) ----------------
    const float4 z = make_float4(0.f, 0.f, 0.f, 0.f);
    #pragma unroll 4
    for (int t = lane; t < n4c; t += 32)
        __stcs(o4 + t, z);

    if (lane < tailc) {                        // tail: exact formula
        int c = head + (n4c << 2) + lane;
        out[base + c] = value_g(x_full, c, n, x);
    }

    // ---- patch window chunks; same lane that zeroed them -----------------
    int cl = (j0 > head) ? ((j0 - head) >> 2) : 0;
    int ch = (j1 >= head) ? ((j1 - head) >> 2) : -1;
    if (ch > n4c - 1) ch = n4c - 1;
    for (int wc = cl; wc <= ch; ++wc) {
        if ((int)(wc & 31) == lane) {
            int c = head + (wc << 2);
            float4 v;
            v.x = value_g(x_full, c,     n, x);
            v.y = value_g(x_full, c + 1, n, x);
            v.z = value_g(x_full, c + 2, n, x);
            v.w = value_g(x_full, c + 3, n, x);
            __stcs(o4 + wc, v);                // overwrites own zero
        }
    }
}

extern "C" void kernel_launch(void* const* d_in, const int* in_sizes, int n_in,
                              void* d_out, int out_size) {
    const float* x_eval = (const float*)d_in[0];  // (n_points, 1) float32
    const float* x_full = (const float*)d_in[1];  // (n_full,)    float32 sorted
    float* out = (float*)d_out;                   // (n_points, n_full) float32

    int n_points = in_sizes[0];
    int n_full   = in_sizes[1];

    int threads = 256;                            // 8 rows per block
    int blocks  = (n_points * 32 + threads - 1) / threads;

    fused_kernel<<<blocks, threads>>>(x_eval, x_full, out, n_points, n_full);
}